// round 2
// baseline (speedup 1.0000x reference)
#include <cuda_runtime.h>
#include <math.h>

// Problem constants (hardcoded for this bespoke problem)
constexpr int NB  = 4;     // batch
constexpr int NT  = 1024;  // tokens
constexpr int ND  = 512;   // model dim
constexpr int NH  = 8;     // heads
constexpr int NL  = 6;     // layers
constexpr int NFF = 2048;  // ffn dim
constexpr int NDH = 64;    // head dim
constexpr float NEG_INF = -1000000000.0f;
constexpr float R2      = 100.0f;
constexpr float EPS_LN  = 1e-5f;

// Scratch (static device globals — no dynamic allocation allowed)
__device__ float g_x [NB*NT*ND];
__device__ float g_h [NB*NT*ND];
__device__ float g_q [NB*NT*ND];
__device__ float g_k [NB*NT*ND];
__device__ float g_v [NB*NT*ND];
__device__ float g_o [NB*NT*ND];
__device__ float g_ff[NB*NT*NFF];
__device__ float g_bias  [(long)NB*NT*NT];
__device__ float g_scores[(long)NB*NH*NT*NT];

// ---------------------------------------------------------------------------
// Copy tokens into the residual-stream buffer
__global__ void copy_x_kernel(const float* __restrict__ src) {
    long i = (long)blockIdx.x * blockDim.x + threadIdx.x;
    g_x[i] = src[i];
}

// ---------------------------------------------------------------------------
// Additive attention bias (B,N,N): dead keys + locality + cross-species
__global__ void build_bias_kernel(const float* __restrict__ xy,
                                  const int* __restrict__ alive,
                                  const int* __restrict__ species) {
    int b = blockIdx.y;
    int i = blockIdx.x;
    float xi = xy[((long)b*NT + i)*2 + 0];
    float yi = xy[((long)b*NT + i)*2 + 1];
    int si = species[(long)b*NT + i];
    bool ia_i = (si < 2), ip_i = (si == 2);
    for (int j = threadIdx.x; j < NT; j += blockDim.x) {
        float dx = xi - xy[((long)b*NT + j)*2 + 0];
        float dy = yi - xy[((long)b*NT + j)*2 + 1];
        float d2 = dx*dx + dy*dy;
        int sj = species[(long)b*NT + j];
        bool ia_j = (sj < 2), ip_j = (sj == 2);
        float bias = 0.0f;
        if (alive[(long)b*NT + j] == 0) bias += NEG_INF;
        if (d2 > R2)                    bias += NEG_INF;
        if ((ia_i && ip_j) || (ip_i && ia_j)) bias += NEG_INF;
        g_bias[((long)b*NT + i)*NT + j] = bias;
    }
}

// ---------------------------------------------------------------------------
// LayerNorm over last dim (512). One block per row, 256 threads x 2 elems.
__global__ void ln_kernel(const float* __restrict__ x,
                          const float* __restrict__ g,
                          const float* __restrict__ be,
                          float* __restrict__ out) {
    __shared__ float sh[8];
    long row = blockIdx.x;
    const float* xr = x + row*ND;
    int t = threadIdx.x;
    float v0 = xr[t], v1 = xr[t + 256];

    float s = v0 + v1;
    #pragma unroll
    for (int o = 16; o > 0; o >>= 1) s += __shfl_xor_sync(0xffffffffu, s, o);
    if ((t & 31) == 0) sh[t >> 5] = s;
    __syncthreads();
    if (t < 8) {
        float w = sh[t];
        #pragma unroll
        for (int o = 4; o > 0; o >>= 1) w += __shfl_xor_sync(0xffu, w, o);
        if (t == 0) sh[0] = w;
    }
    __syncthreads();
    float mean = sh[0] * (1.0f / ND);
    __syncthreads();

    float d0 = v0 - mean, d1 = v1 - mean;
    float q = d0*d0 + d1*d1;
    #pragma unroll
    for (int o = 16; o > 0; o >>= 1) q += __shfl_xor_sync(0xffffffffu, q, o);
    if ((t & 31) == 0) sh[t >> 5] = q;
    __syncthreads();
    if (t < 8) {
        float w = sh[t];
        #pragma unroll
        for (int o = 4; o > 0; o >>= 1) w += __shfl_xor_sync(0xffu, w, o);
        if (t == 0) sh[0] = w;
    }
    __syncthreads();
    float rstd = rsqrtf(sh[0] * (1.0f / ND) + EPS_LN);

    out[row*ND + t]       = d0 * rstd * g[t]       + be[t];
    out[row*ND + t + 256] = d1 * rstd * g[t + 256] + be[t + 256];
}

// ---------------------------------------------------------------------------
// Row softmax over g_scores (rows of length 1024). One block per row.
__global__ void softmax_kernel() {
    __shared__ float sh[8];
    long row = blockIdx.x;
    float* sr = g_scores + row*NT;
    int t = threadIdx.x;
    float v[4];
    #pragma unroll
    for (int i = 0; i < 4; i++) v[i] = sr[t + i*256];

    float m = fmaxf(fmaxf(v[0], v[1]), fmaxf(v[2], v[3]));
    #pragma unroll
    for (int o = 16; o > 0; o >>= 1) m = fmaxf(m, __shfl_xor_sync(0xffffffffu, m, o));
    if ((t & 31) == 0) sh[t >> 5] = m;
    __syncthreads();
    if (t < 8) {
        float w = sh[t];
        #pragma unroll
        for (int o = 4; o > 0; o >>= 1) w = fmaxf(w, __shfl_xor_sync(0xffu, w, o));
        if (t == 0) sh[0] = w;
    }
    __syncthreads();
    float M = sh[0];
    __syncthreads();

    float s = 0.0f;
    #pragma unroll
    for (int i = 0; i < 4; i++) { v[i] = expf(v[i] - M); s += v[i]; }
    #pragma unroll
    for (int o = 16; o > 0; o >>= 1) s += __shfl_xor_sync(0xffffffffu, s, o);
    if ((t & 31) == 0) sh[t >> 5] = s;
    __syncthreads();
    if (t < 8) {
        float w = sh[t];
        #pragma unroll
        for (int o = 4; o > 0; o >>= 1) w += __shfl_xor_sync(0xffu, w, o);
        if (t == 0) sh[0] = w;
    }
    __syncthreads();
    float inv = 1.0f / sh[0];
    #pragma unroll
    for (int i = 0; i < 4; i++) sr[t + i*256] = v[i] * inv;
}

// ---------------------------------------------------------------------------
// Generic tiled fp32 GEMM: C[M,Ncols] = epi(A[M,K] @ B)  (+ variants)
// BM=BN=64, BK=16, 256 threads, 4x4 register micro-tile.
// TRANSB: B accessed as B[n*ldb + k] (i.e. C = A @ B^T)
// EPI: 0 = plain store
//      1 = + bvec[col] + res[row*ldc+col]   (projection with bias + residual)
//      2 = gelu(acc + bvec[col])            (ffn1)
//      3 = acc*alpha + biasmat              (attention scores)
// BATCH (blockIdx.z = b*NH + h):
//      0 = none, 1 = QK^T (A,B are q/k head views; C = scores[z]),
//      2 = P@V (A = scores[z]; B,C head views of v/o)
template<bool TRANSB, int EPI, int BATCH>
__global__ void __launch_bounds__(256)
gemm64(const float* __restrict__ A, const float* __restrict__ Bm,
       float* __restrict__ C,
       int M, int Ncols, int K, int lda, int ldb, int ldc,
       float alpha,
       const float* __restrict__ bvec,
       const float* __restrict__ res,
       const float* __restrict__ bmat) {
    __shared__ float As[16][68];
    __shared__ float Bs[16][68];

    int z = blockIdx.z;
    if (BATCH == 1) {
        int b = z >> 3, h = z & 7;
        long oq = (long)b*NT*ND + (long)h*NDH;
        A += oq; Bm += oq; C += (long)z*NT*NT;
    } else if (BATCH == 2) {
        int b = z >> 3, h = z & 7;
        long ov = (long)b*NT*ND + (long)h*NDH;
        A += (long)z*NT*NT; Bm += ov; C += ov;
    }

    int tid = threadIdx.x;
    int tx = tid & 15, ty = tid >> 4;
    int row0 = blockIdx.y << 6;
    int col0 = blockIdx.x << 6;

    float acc[4][4];
    #pragma unroll
    for (int i = 0; i < 4; i++)
        #pragma unroll
        for (int j = 0; j < 4; j++) acc[i][j] = 0.0f;

    int la_r = tid >> 2;          // 0..63
    int la_k = (tid & 3) << 2;    // 0,4,8,12
    int lb_k = tid >> 4;          // 0..15
    int lb_n = (tid & 15) << 2;   // 0..60

    for (int k0 = 0; k0 < K; k0 += 16) {
        float4 av = *(const float4*)(A + (long)(row0 + la_r)*lda + (k0 + la_k));
        As[la_k + 0][la_r] = av.x;
        As[la_k + 1][la_r] = av.y;
        As[la_k + 2][la_r] = av.z;
        As[la_k + 3][la_r] = av.w;
        if (TRANSB) {
            float4 bv = *(const float4*)(Bm + (long)(col0 + la_r)*ldb + (k0 + la_k));
            Bs[la_k + 0][la_r] = bv.x;
            Bs[la_k + 1][la_r] = bv.y;
            Bs[la_k + 2][la_r] = bv.z;
            Bs[la_k + 3][la_r] = bv.w;
        } else {
            float4 bv = *(const float4*)(Bm + (long)(k0 + lb_k)*ldb + (col0 + lb_n));
            *(float4*)&Bs[lb_k][lb_n] = bv;
        }
        __syncthreads();
        #pragma unroll
        for (int kk = 0; kk < 16; kk++) {
            float4 a4 = *(const float4*)&As[kk][ty << 2];
            float4 b4 = *(const float4*)&Bs[kk][tx << 2];
            float aa[4] = {a4.x, a4.y, a4.z, a4.w};
            float bb[4] = {b4.x, b4.y, b4.z, b4.w};
            #pragma unroll
            for (int i = 0; i < 4; i++)
                #pragma unroll
                for (int j = 0; j < 4; j++) acc[i][j] += aa[i]*bb[j];
        }
        __syncthreads();
    }

    #pragma unroll
    for (int i = 0; i < 4; i++) {
        int r = row0 + (ty << 2) + i;
        #pragma unroll
        for (int j = 0; j < 4; j++) {
            int c = col0 + (tx << 2) + j;
            float val = acc[i][j];
            if (EPI == 1) {
                val += bvec[c] + res[(long)r*ldc + c];
            } else if (EPI == 2) {
                float u = val + bvec[c];
                val = 0.5f * u * (1.0f + erff(u * 0.70710678118654752f));
            } else if (EPI == 3) {
                val = val * alpha + bmat[(long)(z >> 3)*NT*NT + (long)r*NT + c];
            }
            C[(long)r*ldc + c] = val;
        }
    }
}

// ---------------------------------------------------------------------------
extern "C" void kernel_launch(void* const* d_in, const int* in_sizes, int n_in,
                              void* d_out, int out_size) {
    const float* tokens  = (const float*)d_in[0];
    const float* xy      = (const float*)d_in[1];
    const float* Wq      = (const float*)d_in[2];
    const float* Wk      = (const float*)d_in[3];
    const float* Wv      = (const float*)d_in[4];
    const float* Wo      = (const float*)d_in[5];
    const float* bo      = (const float*)d_in[6];
    const float* W1      = (const float*)d_in[7];
    const float* b1      = (const float*)d_in[8];
    const float* W2      = (const float*)d_in[9];
    const float* b2      = (const float*)d_in[10];
    const float* g1      = (const float*)d_in[11];
    const float* be1     = (const float*)d_in[12];
    const float* g2      = (const float*)d_in[13];
    const float* be2     = (const float*)d_in[14];
    const float* gf      = (const float*)d_in[15];
    const float* bf      = (const float*)d_in[16];
    const int*   alive   = (const int*)d_in[17];
    const int*   species = (const int*)d_in[18];
    float* out = (float*)d_out;

    float *px, *ph, *pq, *pk, *pv, *po, *pff, *pbias, *pscores;
    cudaGetSymbolAddress((void**)&px,      g_x);
    cudaGetSymbolAddress((void**)&ph,      g_h);
    cudaGetSymbolAddress((void**)&pq,      g_q);
    cudaGetSymbolAddress((void**)&pk,      g_k);
    cudaGetSymbolAddress((void**)&pv,      g_v);
    cudaGetSymbolAddress((void**)&po,      g_o);
    cudaGetSymbolAddress((void**)&pff,     g_ff);
    cudaGetSymbolAddress((void**)&pbias,   g_bias);
    cudaGetSymbolAddress((void**)&pscores, g_scores);

    const int M = NB * NT;  // 4096 rows

    copy_x_kernel<<<(NB*NT*ND)/256, 256>>>(tokens);
    build_bias_kernel<<<dim3(NT, NB), 256>>>(xy, alive, species);

    for (int l = 0; l < NL; l++) {
        // ln1
        ln_kernel<<<M, 256>>>(px, g1 + (long)l*ND, be1 + (long)l*ND, ph);
        // q, k, v projections (no bias)
        gemm64<false, 0, 0><<<dim3(8, 64), 256>>>(ph, Wq + (long)l*ND*ND, pq,
            M, ND, ND, ND, ND, ND, 1.0f, nullptr, nullptr, nullptr);
        gemm64<false, 0, 0><<<dim3(8, 64), 256>>>(ph, Wk + (long)l*ND*ND, pk,
            M, ND, ND, ND, ND, ND, 1.0f, nullptr, nullptr, nullptr);
        gemm64<false, 0, 0><<<dim3(8, 64), 256>>>(ph, Wv + (long)l*ND*ND, pv,
            M, ND, ND, ND, ND, ND, 1.0f, nullptr, nullptr, nullptr);
        // scores = QK^T/8 + bias   (per b,h)
        gemm64<true, 3, 1><<<dim3(16, 16, NB*NH), 256>>>(pq, pk, pscores,
            NT, NT, NDH, ND, ND, NT, 0.125f, nullptr, nullptr, pbias);
        // softmax rows
        softmax_kernel<<<NB*NH*NT, 256>>>();
        // o = P @ V   (per b,h)
        gemm64<false, 0, 2><<<dim3(1, 16, NB*NH), 256>>>(pscores, pv, po,
            NT, NDH, NT, NT, ND, ND, 1.0f, nullptr, nullptr, nullptr);
        // x = x + o @ Wo + bo
        gemm64<false, 1, 0><<<dim3(8, 64), 256>>>(po, Wo + (long)l*ND*ND, px,
            M, ND, ND, ND, ND, ND, 1.0f, bo + (long)l*ND, px, nullptr);
        // ln2
        ln_kernel<<<M, 256>>>(px, g2 + (long)l*ND, be2 + (long)l*ND, ph);
        // ff = gelu(h @ W1 + b1)
        gemm64<false, 2, 0><<<dim3(32, 64), 256>>>(ph, W1 + (long)l*ND*NFF, pff,
            M, NFF, ND, ND, NFF, NFF, 1.0f, b1 + (long)l*NFF, nullptr, nullptr);
        // x = x + ff @ W2 + b2
        gemm64<false, 1, 0><<<dim3(8, 64), 256>>>(pff, W2 + (long)l*NFF*ND, px,
            M, ND, NFF, NFF, ND, ND, 1.0f, b2 + (long)l*ND, px, nullptr);
    }

    // final LN -> output
    ln_kernel<<<M, 256>>>(px, gf, bf, out);
}

// round 5
// speedup vs baseline: 2.0360x; 2.0360x over previous
#include <cuda_runtime.h>
#include <cuda_bf16.h>
#include <math.h>

// Problem constants
constexpr int NB  = 4;
constexpr int NT  = 1024;
constexpr int ND  = 512;
constexpr int NH  = 8;
constexpr int NL  = 6;
constexpr int NFF = 2048;
constexpr int NDH = 64;
constexpr float NEG_INF = -1000000000.0f;
constexpr float R2      = 100.0f;
constexpr float EPS_LN  = 1e-5f;

// Scratch (static device globals)
__device__ float g_x [NB*NT*ND];
__device__ float g_h [NB*NT*ND];
__device__ float g_q [NB*NT*ND];
__device__ float g_k [NB*NT*ND];
__device__ float g_v [NB*NT*ND];
__device__ float g_o [NB*NT*ND];
__device__ float g_ff[NB*NT*NFF];
__device__ float g_bias  [(long)NB*NT*NT];
__device__ float g_scores[(long)NB*NH*NT*NT];

// ---------------------------------------------------------------------------
__global__ void copy_x_kernel(const float* __restrict__ src) {
    long i = (long)blockIdx.x * blockDim.x + threadIdx.x;
    g_x[i] = src[i];
}

// ---------------------------------------------------------------------------
__global__ void build_bias_kernel(const float* __restrict__ xy,
                                  const int* __restrict__ alive,
                                  const int* __restrict__ species) {
    int b = blockIdx.y;
    int i = blockIdx.x;
    float xi = xy[((long)b*NT + i)*2 + 0];
    float yi = xy[((long)b*NT + i)*2 + 1];
    int si = species[(long)b*NT + i];
    bool ia_i = (si < 2), ip_i = (si == 2);
    for (int j = threadIdx.x; j < NT; j += blockDim.x) {
        float dx = xi - xy[((long)b*NT + j)*2 + 0];
        float dy = yi - xy[((long)b*NT + j)*2 + 1];
        float d2 = dx*dx + dy*dy;
        int sj = species[(long)b*NT + j];
        bool ia_j = (sj < 2), ip_j = (sj == 2);
        float bias = 0.0f;
        if (alive[(long)b*NT + j] == 0) bias += NEG_INF;
        if (d2 > R2)                    bias += NEG_INF;
        if ((ia_i && ip_j) || (ip_i && ia_j)) bias += NEG_INF;
        g_bias[((long)b*NT + i)*NT + j] = bias;
    }
}

// ---------------------------------------------------------------------------
__global__ void ln_kernel(const float* __restrict__ x,
                          const float* __restrict__ g,
                          const float* __restrict__ be,
                          float* __restrict__ out) {
    __shared__ float sh[8];
    long row = blockIdx.x;
    const float* xr = x + row*ND;
    int t = threadIdx.x;
    float v0 = xr[t], v1 = xr[t + 256];

    float s = v0 + v1;
    #pragma unroll
    for (int o = 16; o > 0; o >>= 1) s += __shfl_xor_sync(0xffffffffu, s, o);
    if ((t & 31) == 0) sh[t >> 5] = s;
    __syncthreads();
    if (t < 8) {
        float w = sh[t];
        #pragma unroll
        for (int o = 4; o > 0; o >>= 1) w += __shfl_xor_sync(0xffu, w, o);
        if (t == 0) sh[0] = w;
    }
    __syncthreads();
    float mean = sh[0] * (1.0f / ND);
    __syncthreads();

    float d0 = v0 - mean, d1 = v1 - mean;
    float q = d0*d0 + d1*d1;
    #pragma unroll
    for (int o = 16; o > 0; o >>= 1) q += __shfl_xor_sync(0xffffffffu, q, o);
    if ((t & 31) == 0) sh[t >> 5] = q;
    __syncthreads();
    if (t < 8) {
        float w = sh[t];
        #pragma unroll
        for (int o = 4; o > 0; o >>= 1) w += __shfl_xor_sync(0xffu, w, o);
        if (t == 0) sh[0] = w;
    }
    __syncthreads();
    float rstd = rsqrtf(sh[0] * (1.0f / ND) + EPS_LN);

    out[row*ND + t]       = d0 * rstd * g[t]       + be[t];
    out[row*ND + t + 256] = d1 * rstd * g[t + 256] + be[t + 256];
}

// ---------------------------------------------------------------------------
__global__ void softmax_kernel() {
    __shared__ float sh[8];
    long row = blockIdx.x;
    float* sr = g_scores + row*NT;
    int t = threadIdx.x;
    float v[4];
    #pragma unroll
    for (int i = 0; i < 4; i++) v[i] = sr[t + i*256];

    float m = fmaxf(fmaxf(v[0], v[1]), fmaxf(v[2], v[3]));
    #pragma unroll
    for (int o = 16; o > 0; o >>= 1) m = fmaxf(m, __shfl_xor_sync(0xffffffffu, m, o));
    if ((t & 31) == 0) sh[t >> 5] = m;
    __syncthreads();
    if (t < 8) {
        float w = sh[t];
        #pragma unroll
        for (int o = 4; o > 0; o >>= 1) w = fmaxf(w, __shfl_xor_sync(0xffu, w, o));
        if (t == 0) sh[0] = w;
    }
    __syncthreads();
    float M = sh[0];
    __syncthreads();

    float s = 0.0f;
    #pragma unroll
    for (int i = 0; i < 4; i++) { v[i] = expf(v[i] - M); s += v[i]; }
    #pragma unroll
    for (int o = 16; o > 0; o >>= 1) s += __shfl_xor_sync(0xffffffffu, s, o);
    if ((t & 31) == 0) sh[t >> 5] = s;
    __syncthreads();
    if (t < 8) {
        float w = sh[t];
        #pragma unroll
        for (int o = 4; o > 0; o >>= 1) w += __shfl_xor_sync(0xffu, w, o);
        if (t == 0) sh[0] = w;
    }
    __syncthreads();
    float inv = 1.0f / sh[0];
    #pragma unroll
    for (int i = 0; i < 4; i++) sr[t + i*256] = v[i] * inv;
}

// ---------------------------------------------------------------------------
// bf16 hi/lo helpers
__device__ __forceinline__ void cvt2(float a, float b,
                                     __nv_bfloat16* ph, __nv_bfloat16* pl) {
    __nv_bfloat16 ha = __float2bfloat16(a);
    __nv_bfloat16 hb = __float2bfloat16(b);
    __nv_bfloat16 la = __float2bfloat16(a - __bfloat162float(ha));
    __nv_bfloat16 lb = __float2bfloat16(b - __bfloat162float(hb));
    *(__nv_bfloat162*)ph = __halves2bfloat162(ha, hb);
    *(__nv_bfloat162*)pl = __halves2bfloat162(la, lb);
}

__device__ __forceinline__ void ldsm4(unsigned* r, const __nv_bfloat16* p) {
    unsigned a = (unsigned)__cvta_generic_to_shared(p);
    asm volatile("ldmatrix.sync.aligned.m8n8.x4.shared.b16 {%0,%1,%2,%3}, [%4];"
                 : "=r"(r[0]), "=r"(r[1]), "=r"(r[2]), "=r"(r[3]) : "r"(a));
}
__device__ __forceinline__ void ldsm4t(unsigned* r, const __nv_bfloat16* p) {
    unsigned a = (unsigned)__cvta_generic_to_shared(p);
    asm volatile("ldmatrix.sync.aligned.m8n8.x4.trans.shared.b16 {%0,%1,%2,%3}, [%4];"
                 : "=r"(r[0]), "=r"(r[1]), "=r"(r[2]), "=r"(r[3]) : "r"(a));
}
__device__ __forceinline__ void mma_bf16(float* d, const unsigned* a, const unsigned* b) {
    asm volatile(
        "mma.sync.aligned.m16n8k16.row.col.f32.bf16.bf16.f32 "
        "{%0,%1,%2,%3},{%4,%5,%6,%7},{%8,%9},{%0,%1,%2,%3};"
        : "+f"(d[0]), "+f"(d[1]), "+f"(d[2]), "+f"(d[3])
        : "r"(a[0]), "r"(a[1]), "r"(a[2]), "r"(a[3]), "r"(b[0]), "r"(b[1]));
}

// ---------------------------------------------------------------------------
// Tensor-core GEMM (bf16 hi/lo 3-pass, fp32-grade accuracy):
//   C[M,N] = epi(A[M,K] @ B)
// BM=128, BN template {128,64}, BK=32. 8 warps (4 m x 2 n). Warp tile 32 x BN/2.
// TRANSB: B indexed as B[n*ldb+k] (C = A @ B^T). EPI/BATCH same meanings as R2.
template<int BN, bool TRANSB, int EPI, int BATCH>
__global__ void __launch_bounds__(256)
gemm_mma(const float* __restrict__ A, const float* __restrict__ Bm,
         float* __restrict__ C,
         int M, int Ncols, int K, int lda, int ldb, int ldc,
         float alpha,
         const float* __restrict__ bvec,
         const float* __restrict__ res,
         const float* __restrict__ bmat) {
    constexpr int PADK  = 40;                  // LDSM conflict-free (80B row stride)
    constexpr int BROWS = TRANSB ? BN : 32;
    constexpr int BCOLS = TRANSB ? PADK : (BN + 8);  // (BN+8)*2B stride == 16 mod 128
    constexpr int NTW   = BN / 16;             // n-tiles per warp (8 or 4)

    __shared__ __nv_bfloat16 Ah[128][PADK], Al[128][PADK];
    __shared__ __nv_bfloat16 Bh[BROWS][BCOLS], Bl[BROWS][BCOLS];

    int z = blockIdx.z;
    if (BATCH == 1) {
        int b = z >> 3, h = z & 7;
        long oq = (long)b*NT*ND + (long)h*NDH;
        A += oq; Bm += oq; C += (long)z*NT*NT;
    } else if (BATCH == 2) {
        int b = z >> 3, h = z & 7;
        long ov = (long)b*NT*ND + (long)h*NDH;
        A += (long)z*NT*NT; Bm += ov; C += ov;
    }

    int tid  = threadIdx.x;
    int wid  = tid >> 5, lane = tid & 31;
    int wm   = wid & 3, wn = wid >> 2;
    int wrow = wm * 32;                 // warp m offset in tile
    int wcol = wn * (BN / 2);           // warp n offset in tile
    int row0 = blockIdx.y * 128;
    int col0 = blockIdx.x * BN;

    float acc[2][NTW][4];
    #pragma unroll
    for (int i = 0; i < 2; i++)
        #pragma unroll
        for (int j = 0; j < NTW; j++)
            #pragma unroll
            for (int e = 0; e < 4; e++) acc[i][j][e] = 0.0f;

    // ldmatrix lane-address components (non-trans: A and K-major B)
    int r_ld = (lane & 7) + ((lane >> 3) & 1) * 8;
    int c_ld = (lane >> 4) * 8;

    for (int k0 = 0; k0 < K; k0 += 32) {
        // ---- stage A (128 x 32) ----
        #pragma unroll
        for (int f = tid; f < 128 * 8; f += 256) {
            int row = f >> 3, kk = (f & 7) * 4;
            float4 v = *(const float4*)(A + (long)(row0 + row)*lda + k0 + kk);
            cvt2(v.x, v.y, &Ah[row][kk],   &Al[row][kk]);
            cvt2(v.z, v.w, &Ah[row][kk+2], &Al[row][kk+2]);
        }
        // ---- stage B ----
        if (TRANSB) {  // B[n][k] rows, direct
            #pragma unroll
            for (int f = tid; f < BN * 8; f += 256) {
                int row = f >> 3, kk = (f & 7) * 4;
                float4 v = *(const float4*)(Bm + (long)(col0 + row)*ldb + k0 + kk);
                cvt2(v.x, v.y, &Bh[row][kk],   &Bl[row][kk]);
                cvt2(v.z, v.w, &Bh[row][kk+2], &Bl[row][kk+2]);
            }
        } else {       // B[k][n], keep k-major; .trans ldmatrix does the transpose
            #pragma unroll
            for (int f = tid; f < 32 * (BN/4); f += 256) {
                int krow = f / (BN/4);
                int nc   = (f % (BN/4)) * 4;
                float4 v = *(const float4*)(Bm + (long)(k0 + krow)*ldb + col0 + nc);
                cvt2(v.x, v.y, &Bh[krow][nc],   &Bl[krow][nc]);
                cvt2(v.z, v.w, &Bh[krow][nc+2], &Bl[krow][nc+2]);
            }
        }
        __syncthreads();

        #pragma unroll
        for (int ks = 0; ks < 2; ks++) {
            unsigned afr[2][2][4];    // [mt][hi/lo][4]
            unsigned bfr[NTW][2][2];  // [nt][hi/lo][2]
            #pragma unroll
            for (int mt = 0; mt < 2; mt++) {
                ldsm4(afr[mt][0], &Ah[wrow + mt*16 + r_ld][ks*16 + c_ld]);
                ldsm4(afr[mt][1], &Al[wrow + mt*16 + r_ld][ks*16 + c_ld]);
            }
            #pragma unroll
            for (int np = 0; np < NTW/2; np++) {
                if (TRANSB) {
                    // tiles: {nt0 k0-7, nt0 k8-15, nt1 k0-7, nt1 k8-15}
                    int nrow = wcol + np*16 + (lane >> 4)*8 + (lane & 7);
                    int kcol = ks*16 + ((lane >> 3) & 1)*8;
                    unsigned r[4];
                    ldsm4(r, &Bh[nrow][kcol]);
                    bfr[2*np][0][0] = r[0]; bfr[2*np][0][1] = r[1];
                    bfr[2*np+1][0][0] = r[2]; bfr[2*np+1][0][1] = r[3];
                    ldsm4(r, &Bl[nrow][kcol]);
                    bfr[2*np][1][0] = r[0]; bfr[2*np][1][1] = r[1];
                    bfr[2*np+1][1][0] = r[2]; bfr[2*np+1][1][1] = r[3];
                } else {
                    int krow = ks*16 + ((lane >> 3) & 1)*8 + (lane & 7);
                    int ncol = wcol + np*16 + (lane >> 4)*8;
                    unsigned r[4];
                    ldsm4t(r, &Bh[krow][ncol]);
                    bfr[2*np][0][0] = r[0]; bfr[2*np][0][1] = r[1];
                    bfr[2*np+1][0][0] = r[2]; bfr[2*np+1][0][1] = r[3];
                    ldsm4t(r, &Bl[krow][ncol]);
                    bfr[2*np][1][0] = r[0]; bfr[2*np][1][1] = r[1];
                    bfr[2*np+1][1][0] = r[2]; bfr[2*np+1][1][1] = r[3];
                }
            }
            #pragma unroll
            for (int mt = 0; mt < 2; mt++)
                #pragma unroll
                for (int nt = 0; nt < NTW; nt++) {
                    mma_bf16(acc[mt][nt], afr[mt][0], bfr[nt][0]);  // Ah*Bh
                    mma_bf16(acc[mt][nt], afr[mt][0], bfr[nt][1]);  // Ah*Bl
                    mma_bf16(acc[mt][nt], afr[mt][1], bfr[nt][0]);  // Al*Bh
                }
        }
        __syncthreads();
    }

    // ---- epilogue ----
    int gid = lane >> 2, tig = lane & 3;
    #pragma unroll
    for (int mt = 0; mt < 2; mt++) {
        #pragma unroll
        for (int nt = 0; nt < NTW; nt++) {
            int r = row0 + wrow + mt*16 + gid;
            int c = col0 + wcol + nt*8 + 2*tig;
            #pragma unroll
            for (int half = 0; half < 2; half++) {
                int rr = r + half*8;
                float d0 = acc[mt][nt][2*half + 0];
                float d1 = acc[mt][nt][2*half + 1];
                if (EPI == 1) {
                    d0 += bvec[c]   + res[(long)rr*ldc + c];
                    d1 += bvec[c+1] + res[(long)rr*ldc + c + 1];
                } else if (EPI == 2) {
                    float u0 = d0 + bvec[c],   u1 = d1 + bvec[c+1];
                    d0 = 0.5f * u0 * (1.0f + erff(u0 * 0.70710678118654752f));
                    d1 = 0.5f * u1 * (1.0f + erff(u1 * 0.70710678118654752f));
                } else if (EPI == 3) {
                    long bofs = (long)(z >> 3)*NT*NT + (long)rr*NT + c;
                    d0 = d0 * alpha + bmat[bofs];
                    d1 = d1 * alpha + bmat[bofs + 1];
                }
                *(float2*)(C + (long)rr*ldc + c) = make_float2(d0, d1);
            }
        }
    }
}

// ---------------------------------------------------------------------------
extern "C" void kernel_launch(void* const* d_in, const int* in_sizes, int n_in,
                              void* d_out, int out_size) {
    const float* tokens  = (const float*)d_in[0];
    const float* xy      = (const float*)d_in[1];
    const float* Wq      = (const float*)d_in[2];
    const float* Wk      = (const float*)d_in[3];
    const float* Wv      = (const float*)d_in[4];
    const float* Wo      = (const float*)d_in[5];
    const float* bo      = (const float*)d_in[6];
    const float* W1      = (const float*)d_in[7];
    const float* b1      = (const float*)d_in[8];
    const float* W2      = (const float*)d_in[9];
    const float* b2      = (const float*)d_in[10];
    const float* g1      = (const float*)d_in[11];
    const float* be1     = (const float*)d_in[12];
    const float* g2      = (const float*)d_in[13];
    const float* be2     = (const float*)d_in[14];
    const float* gf      = (const float*)d_in[15];
    const float* bf      = (const float*)d_in[16];
    const int*   alive   = (const int*)d_in[17];
    const int*   species = (const int*)d_in[18];
    float* out = (float*)d_out;

    float *px, *ph, *pq, *pk, *pv, *po, *pff, *pbias, *pscores;
    cudaGetSymbolAddress((void**)&px,      g_x);
    cudaGetSymbolAddress((void**)&ph,      g_h);
    cudaGetSymbolAddress((void**)&pq,      g_q);
    cudaGetSymbolAddress((void**)&pk,      g_k);
    cudaGetSymbolAddress((void**)&pv,      g_v);
    cudaGetSymbolAddress((void**)&po,      g_o);
    cudaGetSymbolAddress((void**)&pff,     g_ff);
    cudaGetSymbolAddress((void**)&pbias,   g_bias);
    cudaGetSymbolAddress((void**)&pscores, g_scores);

    const int M = NB * NT;  // 4096

    copy_x_kernel<<<(NB*NT*ND)/256, 256>>>(tokens);
    build_bias_kernel<<<dim3(NT, NB), 256>>>(xy, alive, species);

    for (int l = 0; l < NL; l++) {
        ln_kernel<<<M, 256>>>(px, g1 + (long)l*ND, be1 + (long)l*ND, ph);
        // QKV projections
        gemm_mma<128, false, 0, 0><<<dim3(4, 32), 256>>>(ph, Wq + (long)l*ND*ND, pq,
            M, ND, ND, ND, ND, ND, 1.0f, nullptr, nullptr, nullptr);
        gemm_mma<128, false, 0, 0><<<dim3(4, 32), 256>>>(ph, Wk + (long)l*ND*ND, pk,
            M, ND, ND, ND, ND, ND, 1.0f, nullptr, nullptr, nullptr);
        gemm_mma<128, false, 0, 0><<<dim3(4, 32), 256>>>(ph, Wv + (long)l*ND*ND, pv,
            M, ND, ND, ND, ND, ND, 1.0f, nullptr, nullptr, nullptr);
        // scores = QK^T/8 + bias
        gemm_mma<128, true, 3, 1><<<dim3(8, 8, NB*NH), 256>>>(pq, pk, pscores,
            NT, NT, NDH, ND, ND, NT, 0.125f, nullptr, nullptr, pbias);
        softmax_kernel<<<NB*NH*NT, 256>>>();
        // o = P @ V
        gemm_mma<64, false, 0, 2><<<dim3(1, 8, NB*NH), 256>>>(pscores, pv, po,
            NT, NDH, NT, NT, ND, ND, 1.0f, nullptr, nullptr, nullptr);
        // x = x + o @ Wo + bo
        gemm_mma<128, false, 1, 0><<<dim3(4, 32), 256>>>(po, Wo + (long)l*ND*ND, px,
            M, ND, ND, ND, ND, ND, 1.0f, bo + (long)l*ND, px, nullptr);
        ln_kernel<<<M, 256>>>(px, g2 + (long)l*ND, be2 + (long)l*ND, ph);
        // ff = gelu(h @ W1 + b1)
        gemm_mma<128, false, 2, 0><<<dim3(16, 32), 256>>>(ph, W1 + (long)l*ND*NFF, pff,
            M, NFF, ND, ND, NFF, NFF, 1.0f, b1 + (long)l*NFF, nullptr, nullptr);
        // x = x + ff @ W2 + b2
        gemm_mma<128, false, 1, 0><<<dim3(4, 32), 256>>>(pff, W2 + (long)l*NFF*ND, px,
            M, ND, NFF, NFF, ND, ND, 1.0f, b2 + (long)l*ND, px, nullptr);
    }

    ln_kernel<<<M, 256>>>(px, gf, bf, out);
}

// round 6
// speedup vs baseline: 2.4006x; 1.1791x over previous
#include <cuda_runtime.h>
#include <cuda_bf16.h>
#include <math.h>

typedef __nv_bfloat16 bf16;

// Problem constants
constexpr int NB  = 4;
constexpr int NT  = 1024;
constexpr int ND  = 512;
constexpr int NH  = 8;
constexpr int NL  = 6;
constexpr int NFF = 2048;
constexpr int NDH = 64;
constexpr int N3  = 3 * ND;   // 1536 (fused QKV width)
constexpr float NEG_INF = -1000000000.0f;
constexpr float R2      = 100.0f;
constexpr float EPS_LN  = 1e-5f;

// fp32 state
__device__ float g_x     [NB*NT*ND];
__device__ float g_bias  [(long)NB*NT*NT];
__device__ float g_scores[(long)NB*NH*NT*NT];

// bf16 hi/lo activations
__device__ bf16 g_hh [NB*NT*ND],  g_hl [NB*NT*ND];
__device__ bf16 g_qkvh[NB*NT*N3], g_qkvl[NB*NT*N3];
__device__ bf16 g_ph [(long)NB*NH*NT*NT], g_pl[(long)NB*NH*NT*NT];
__device__ bf16 g_oh [NB*NT*ND],  g_ol [NB*NT*ND];
__device__ bf16 g_ffh[NB*NT*NFF], g_ffl[NB*NT*NFF];

// bf16 hi/lo weights (converted once per launch)
__device__ bf16 g_wqkvh[NL*ND*N3], g_wqkvl[NL*ND*N3];
__device__ bf16 g_woh [NL*ND*ND],  g_wol [NL*ND*ND];
__device__ bf16 g_w1h [NL*ND*NFF], g_w1l [NL*ND*NFF];
__device__ bf16 g_w2h [NL*NFF*ND], g_w2l [NL*NFF*ND];

// ---------------------------------------------------------------------------
__device__ __forceinline__ void split1(float v, bf16& h, bf16& l) {
    h = __float2bfloat16(v);
    l = __float2bfloat16(v - __bfloat162float(h));
}

__global__ void copy_x_kernel(const float* __restrict__ src) {
    long i = (long)blockIdx.x * blockDim.x + threadIdx.x;
    g_x[i] = src[i];
}

__global__ void convert_flat(const float* __restrict__ s,
                             bf16* __restrict__ h, bf16* __restrict__ l) {
    long i = (long)blockIdx.x * 256 + threadIdx.x;
    split1(s[i], h[i], l[i]);
}

__global__ void convert_qkv(const float* __restrict__ Wq,
                            const float* __restrict__ Wk,
                            const float* __restrict__ Wv) {
    long i = (long)blockIdx.x * 256 + threadIdx.x;   // over NL*ND*N3
    int n = (int)(i % N3);
    long rem = i / N3;                                // l*ND + k
    const float* src = (n < ND) ? Wq : (n < 2*ND ? Wk : Wv);
    int nn = n & (ND - 1);
    split1(src[rem*ND + nn], g_wqkvh[i], g_wqkvl[i]);
}

// ---------------------------------------------------------------------------
__global__ void build_bias_kernel(const float* __restrict__ xy,
                                  const int* __restrict__ alive,
                                  const int* __restrict__ species) {
    int b = blockIdx.y;
    int i = blockIdx.x;
    float xi = xy[((long)b*NT + i)*2 + 0];
    float yi = xy[((long)b*NT + i)*2 + 1];
    int si = species[(long)b*NT + i];
    bool ia_i = (si < 2), ip_i = (si == 2);
    for (int j = threadIdx.x; j < NT; j += blockDim.x) {
        float dx = xi - xy[((long)b*NT + j)*2 + 0];
        float dy = yi - xy[((long)b*NT + j)*2 + 1];
        float d2 = dx*dx + dy*dy;
        int sj = species[(long)b*NT + j];
        bool ia_j = (sj < 2), ip_j = (sj == 2);
        float bias = 0.0f;
        if (alive[(long)b*NT + j] == 0) bias += NEG_INF;
        if (d2 > R2)                    bias += NEG_INF;
        if ((ia_i && ip_j) || (ip_i && ia_j)) bias += NEG_INF;
        g_bias[((long)b*NT + i)*NT + j] = bias;
    }
}

// ---------------------------------------------------------------------------
// LayerNorm; BF=true -> bf16 hi/lo outputs, else fp32.
template<bool BF>
__global__ void ln_kernel(const float* __restrict__ x,
                          const float* __restrict__ g,
                          const float* __restrict__ be,
                          float* __restrict__ outf,
                          bf16* __restrict__ outh, bf16* __restrict__ outl) {
    __shared__ float sh[8];
    long row = blockIdx.x;
    const float* xr = x + row*ND;
    int t = threadIdx.x;
    float v0 = xr[t], v1 = xr[t + 256];

    float s = v0 + v1;
    #pragma unroll
    for (int o = 16; o > 0; o >>= 1) s += __shfl_xor_sync(0xffffffffu, s, o);
    if ((t & 31) == 0) sh[t >> 5] = s;
    __syncthreads();
    if (t < 8) {
        float w = sh[t];
        #pragma unroll
        for (int o = 4; o > 0; o >>= 1) w += __shfl_xor_sync(0xffu, w, o);
        if (t == 0) sh[0] = w;
    }
    __syncthreads();
    float mean = sh[0] * (1.0f / ND);
    __syncthreads();

    float d0 = v0 - mean, d1 = v1 - mean;
    float q = d0*d0 + d1*d1;
    #pragma unroll
    for (int o = 16; o > 0; o >>= 1) q += __shfl_xor_sync(0xffffffffu, q, o);
    if ((t & 31) == 0) sh[t >> 5] = q;
    __syncthreads();
    if (t < 8) {
        float w = sh[t];
        #pragma unroll
        for (int o = 4; o > 0; o >>= 1) w += __shfl_xor_sync(0xffu, w, o);
        if (t == 0) sh[0] = w;
    }
    __syncthreads();
    float rstd = rsqrtf(sh[0] * (1.0f / ND) + EPS_LN);

    float r0 = d0 * rstd * g[t]       + be[t];
    float r1 = d1 * rstd * g[t + 256] + be[t + 256];
    if (BF) {
        split1(r0, outh[row*ND + t],       outl[row*ND + t]);
        split1(r1, outh[row*ND + t + 256], outl[row*ND + t + 256]);
    } else {
        outf[row*ND + t]       = r0;
        outf[row*ND + t + 256] = r1;
    }
}

// ---------------------------------------------------------------------------
// Softmax over fp32 scores -> bf16 hi/lo probabilities
__global__ void softmax_kernel() {
    __shared__ float sh[8];
    long row = blockIdx.x;
    const float* sr = g_scores + row*NT;
    int t = threadIdx.x;
    float v[4];
    #pragma unroll
    for (int i = 0; i < 4; i++) v[i] = sr[t + i*256];

    float m = fmaxf(fmaxf(v[0], v[1]), fmaxf(v[2], v[3]));
    #pragma unroll
    for (int o = 16; o > 0; o >>= 1) m = fmaxf(m, __shfl_xor_sync(0xffffffffu, m, o));
    if ((t & 31) == 0) sh[t >> 5] = m;
    __syncthreads();
    if (t < 8) {
        float w = sh[t];
        #pragma unroll
        for (int o = 4; o > 0; o >>= 1) w = fmaxf(w, __shfl_xor_sync(0xffu, w, o));
        if (t == 0) sh[0] = w;
    }
    __syncthreads();
    float M = sh[0];
    __syncthreads();

    float s = 0.0f;
    #pragma unroll
    for (int i = 0; i < 4; i++) { v[i] = expf(v[i] - M); s += v[i]; }
    #pragma unroll
    for (int o = 16; o > 0; o >>= 1) s += __shfl_xor_sync(0xffffffffu, s, o);
    if ((t & 31) == 0) sh[t >> 5] = s;
    __syncthreads();
    if (t < 8) {
        float w = sh[t];
        #pragma unroll
        for (int o = 4; o > 0; o >>= 1) w += __shfl_xor_sync(0xffu, w, o);
        if (t == 0) sh[0] = w;
    }
    __syncthreads();
    float inv = 1.0f / sh[0];
    #pragma unroll
    for (int i = 0; i < 4; i++) {
        float p = v[i] * inv;
        split1(p, g_ph[row*NT + t + i*256], g_pl[row*NT + t + i*256]);
    }
}

// ---------------------------------------------------------------------------
// mma / ldmatrix / cp.async primitives
__device__ __forceinline__ void ldsm4(unsigned* r, const bf16* p) {
    unsigned a = (unsigned)__cvta_generic_to_shared(p);
    asm volatile("ldmatrix.sync.aligned.m8n8.x4.shared.b16 {%0,%1,%2,%3}, [%4];"
                 : "=r"(r[0]), "=r"(r[1]), "=r"(r[2]), "=r"(r[3]) : "r"(a));
}
__device__ __forceinline__ void ldsm4t(unsigned* r, const bf16* p) {
    unsigned a = (unsigned)__cvta_generic_to_shared(p);
    asm volatile("ldmatrix.sync.aligned.m8n8.x4.trans.shared.b16 {%0,%1,%2,%3}, [%4];"
                 : "=r"(r[0]), "=r"(r[1]), "=r"(r[2]), "=r"(r[3]) : "r"(a));
}
__device__ __forceinline__ void mma_bf16(float* d, const unsigned* a, const unsigned* b) {
    asm volatile(
        "mma.sync.aligned.m16n8k16.row.col.f32.bf16.bf16.f32 "
        "{%0,%1,%2,%3},{%4,%5,%6,%7},{%8,%9},{%0,%1,%2,%3};"
        : "+f"(d[0]), "+f"(d[1]), "+f"(d[2]), "+f"(d[3])
        : "r"(a[0]), "r"(a[1]), "r"(a[2]), "r"(a[3]), "r"(b[0]), "r"(b[1]));
}
__device__ __forceinline__ void cpa16(bf16* dst, const bf16* src) {
    unsigned d = (unsigned)__cvta_generic_to_shared(dst);
    asm volatile("cp.async.cg.shared.global [%0], [%1], 16;" :: "r"(d), "l"(src));
}
__device__ __forceinline__ void cp_commit() { asm volatile("cp.async.commit_group;"); }
template<int N>
__device__ __forceinline__ void cp_wait() { asm volatile("cp.async.wait_group %0;" :: "n"(N)); }

// ---------------------------------------------------------------------------
// bf16 hi/lo 3-pass GEMM, cp.async double-buffered, dynamic smem.
// C[M,N] = epi(A @ B).  BK=32, 8 warps: WM=8/WN warps on m, WN on n.
// TRANSB: B indexed B[n*ldb+k] (C = A@B^T).
// EPI: 0 f32 store | 1 +bvec+res -> f32 | 2 gelu -> bf16 hi/lo
//      3 alpha*acc + bias -> f32 | 4 plain -> bf16 hi/lo
// BATCH: 0 none | 1 QK^T over qkv buffer | 2 P@V over qkv buffer
template<int BM, int BN, int WN, bool TRANSB, int EPI, int BATCH>
__global__ void __launch_bounds__(256, 2)
gemm_bf(const bf16* __restrict__ Agh, const bf16* __restrict__ Agl,
        const bf16* __restrict__ Bgh, const bf16* __restrict__ Bgl,
        float* __restrict__ Cf, bf16* __restrict__ Ch, bf16* __restrict__ Cl,
        int M, int K, int lda, int ldb, int ldc, float alpha,
        const float* __restrict__ bvec, const float* __restrict__ res,
        const float* __restrict__ bmat) {
    constexpr int WM    = 8 / WN;
    constexpr int MT    = BM / WM / 16;          // = 2
    constexpr int NTW   = BN / WN / 8;           // 8 or 4
    constexpr int PADK  = 40;
    constexpr int BROWS = TRANSB ? BN : 32;
    constexpr int BCOLS = TRANSB ? PADK : (BN + 8);
    constexpr int AE    = BM * PADK;
    constexpr int BE    = BROWS * BCOLS;
    constexpr int STAGE = 2*AE + 2*BE;

    extern __shared__ bf16 sm[];

    int z = blockIdx.z;
    if (BATCH == 1) {
        int b = z >> 3, h = z & 7;
        long oa = (long)b*NT*N3 + h*NDH;
        long ob = (long)b*NT*N3 + ND + h*NDH;
        Agh += oa; Agl += oa; Bgh += ob; Bgl += ob;
        Cf  += (long)z*NT*NT;
        bmat += (long)b*NT*NT;
    } else if (BATCH == 2) {
        int b = z >> 3, h = z & 7;
        long oa = (long)z*NT*NT;
        long ob = (long)b*NT*N3 + 2*ND + h*NDH;
        long oc = (long)b*NT*ND + h*NDH;
        Agh += oa; Agl += oa; Bgh += ob; Bgl += ob; Ch += oc; Cl += oc;
    }

    int tid = threadIdx.x, wid = tid >> 5, lane = tid & 31;
    int wm = wid % WM, wn = wid / WM;
    int wrow = wm * (BM / WM), wcol = wn * (BN / WN);
    int row0 = blockIdx.y * BM, col0 = blockIdx.x * BN;

    float acc[MT][NTW][4];
    #pragma unroll
    for (int i = 0; i < MT; i++)
        #pragma unroll
        for (int j = 0; j < NTW; j++)
            #pragma unroll
            for (int e = 0; e < 4; e++) acc[i][j][e] = 0.0f;

    int r_ld = (lane & 7) + ((lane >> 3) & 1) * 8;
    int c_ld = (lane >> 4) * 8;

    const int NS = K / 32;

    auto stage = [&](int s, int p) {
        bf16* sAh = sm + p*STAGE;
        bf16* sAl = sAh + AE;
        bf16* sBh = sAh + 2*AE;
        bf16* sBl = sBh + BE;
        int k0 = s * 32;
        #pragma unroll
        for (int f = tid; f < BM*4; f += 256) {
            int row = f >> 2, ck = (f & 3) * 8;
            long go = (long)(row0 + row)*lda + k0 + ck;
            cpa16(sAh + row*PADK + ck, Agh + go);
            cpa16(sAl + row*PADK + ck, Agl + go);
        }
        if (TRANSB) {
            #pragma unroll
            for (int f = tid; f < BN*4; f += 256) {
                int row = f >> 2, ck = (f & 3) * 8;
                long go = (long)(col0 + row)*ldb + k0 + ck;
                cpa16(sBh + row*PADK + ck, Bgh + go);
                cpa16(sBl + row*PADK + ck, Bgl + go);
            }
        } else {
            #pragma unroll
            for (int f = tid; f < 32*(BN/8); f += 256) {
                int row = f / (BN/8), ck = (f % (BN/8)) * 8;
                long go = (long)(k0 + row)*ldb + col0 + ck;
                cpa16(sBh + row*BCOLS + ck, Bgh + go);
                cpa16(sBl + row*BCOLS + ck, Bgl + go);
            }
        }
    };

    stage(0, 0);
    cp_commit();

    for (int s = 0; s < NS; s++) {
        int p = s & 1;
        if (s + 1 < NS) stage(s + 1, p ^ 1);
        cp_commit();
        cp_wait<1>();
        __syncthreads();

        bf16* sAh = sm + p*STAGE;
        bf16* sAl = sAh + AE;
        bf16* sBh = sAh + 2*AE;
        bf16* sBl = sBh + BE;

        #pragma unroll
        for (int ks = 0; ks < 2; ks++) {
            unsigned afr[MT][2][4];
            unsigned bfr[NTW][2][2];
            #pragma unroll
            for (int mt = 0; mt < MT; mt++) {
                ldsm4(afr[mt][0], sAh + (wrow + mt*16 + r_ld)*PADK + ks*16 + c_ld);
                ldsm4(afr[mt][1], sAl + (wrow + mt*16 + r_ld)*PADK + ks*16 + c_ld);
            }
            #pragma unroll
            for (int np = 0; np < NTW/2; np++) {
                unsigned r[4];
                if (TRANSB) {
                    int nrow = wcol + np*16 + (lane >> 4)*8 + (lane & 7);
                    int kcol = ks*16 + ((lane >> 3) & 1)*8;
                    ldsm4(r, sBh + nrow*PADK + kcol);
                    bfr[2*np][0][0] = r[0]; bfr[2*np][0][1] = r[1];
                    bfr[2*np+1][0][0] = r[2]; bfr[2*np+1][0][1] = r[3];
                    ldsm4(r, sBl + nrow*PADK + kcol);
                    bfr[2*np][1][0] = r[0]; bfr[2*np][1][1] = r[1];
                    bfr[2*np+1][1][0] = r[2]; bfr[2*np+1][1][1] = r[3];
                } else {
                    int krow = ks*16 + ((lane >> 3) & 1)*8 + (lane & 7);
                    int ncol = wcol + np*16 + (lane >> 4)*8;
                    ldsm4t(r, sBh + krow*BCOLS + ncol);
                    bfr[2*np][0][0] = r[0]; bfr[2*np][0][1] = r[1];
                    bfr[2*np+1][0][0] = r[2]; bfr[2*np+1][0][1] = r[3];
                    ldsm4t(r, sBl + krow*BCOLS + ncol);
                    bfr[2*np][1][0] = r[0]; bfr[2*np][1][1] = r[1];
                    bfr[2*np+1][1][0] = r[2]; bfr[2*np+1][1][1] = r[3];
                }
            }
            #pragma unroll
            for (int mt = 0; mt < MT; mt++)
                #pragma unroll
                for (int nt = 0; nt < NTW; nt++) {
                    mma_bf16(acc[mt][nt], afr[mt][0], bfr[nt][0]);
                    mma_bf16(acc[mt][nt], afr[mt][0], bfr[nt][1]);
                    mma_bf16(acc[mt][nt], afr[mt][1], bfr[nt][0]);
                }
        }
        __syncthreads();
    }

    // epilogue
    int gid = lane >> 2, tig = lane & 3;
    #pragma unroll
    for (int mt = 0; mt < MT; mt++) {
        #pragma unroll
        for (int nt = 0; nt < NTW; nt++) {
            int r = row0 + wrow + mt*16 + gid;
            int c = col0 + wcol + nt*8 + 2*tig;
            #pragma unroll
            for (int half = 0; half < 2; half++) {
                int rr = r + half*8;
                float d0 = acc[mt][nt][2*half + 0];
                float d1 = acc[mt][nt][2*half + 1];
                long off = (long)rr*ldc + c;
                if (EPI == 0) {
                    *(float2*)(Cf + off) = make_float2(d0, d1);
                } else if (EPI == 1) {
                    d0 += bvec[c]   + res[off];
                    d1 += bvec[c+1] + res[off + 1];
                    *(float2*)(Cf + off) = make_float2(d0, d1);
                } else if (EPI == 2) {
                    float u0 = d0 + bvec[c],   u1 = d1 + bvec[c+1];
                    d0 = 0.5f * u0 * (1.0f + erff(u0 * 0.70710678118654752f));
                    d1 = 0.5f * u1 * (1.0f + erff(u1 * 0.70710678118654752f));
                    bf16 h0, l0, h1, l1;
                    split1(d0, h0, l0); split1(d1, h1, l1);
                    *(__nv_bfloat162*)(Ch + off) = __halves2bfloat162(h0, h1);
                    *(__nv_bfloat162*)(Cl + off) = __halves2bfloat162(l0, l1);
                } else if (EPI == 3) {
                    long bofs = (long)rr*NT + c;
                    d0 = d0 * alpha + bmat[bofs];
                    d1 = d1 * alpha + bmat[bofs + 1];
                    *(float2*)(Cf + off) = make_float2(d0, d1);
                } else {  // EPI == 4
                    bf16 h0, l0, h1, l1;
                    split1(d0, h0, l0); split1(d1, h1, l1);
                    *(__nv_bfloat162*)(Ch + off) = __halves2bfloat162(h0, h1);
                    *(__nv_bfloat162*)(Cl + off) = __halves2bfloat162(l0, l1);
                }
            }
        }
    }
}

// host-side smem size mirror
constexpr int smem_bytes(int BM, int BN, bool TRANSB) {
    return 8 * (BM*40 + (TRANSB ? BN*40 : 32*(BN+8)));
}

// ---------------------------------------------------------------------------
extern "C" void kernel_launch(void* const* d_in, const int* in_sizes, int n_in,
                              void* d_out, int out_size) {
    const float* tokens  = (const float*)d_in[0];
    const float* xy      = (const float*)d_in[1];
    const float* Wq      = (const float*)d_in[2];
    const float* Wk      = (const float*)d_in[3];
    const float* Wv      = (const float*)d_in[4];
    const float* Wo      = (const float*)d_in[5];
    const float* bo      = (const float*)d_in[6];
    const float* W1      = (const float*)d_in[7];
    const float* b1      = (const float*)d_in[8];
    const float* W2      = (const float*)d_in[9];
    const float* b2      = (const float*)d_in[10];
    const float* g1      = (const float*)d_in[11];
    const float* be1     = (const float*)d_in[12];
    const float* g2      = (const float*)d_in[13];
    const float* be2     = (const float*)d_in[14];
    const float* gf      = (const float*)d_in[15];
    const float* bf      = (const float*)d_in[16];
    const int*   alive   = (const int*)d_in[17];
    const int*   species = (const int*)d_in[18];
    float* out = (float*)d_out;

    float *px, *pbias, *pscores;
    cudaGetSymbolAddress((void**)&px,      g_x);
    cudaGetSymbolAddress((void**)&pbias,   g_bias);
    cudaGetSymbolAddress((void**)&pscores, g_scores);
    bf16 *hh,*hl,*qkvh,*qkvl,*ph,*pl,*oh,*ol,*ffh,*ffl;
    cudaGetSymbolAddress((void**)&hh,   g_hh);   cudaGetSymbolAddress((void**)&hl,   g_hl);
    cudaGetSymbolAddress((void**)&qkvh, g_qkvh); cudaGetSymbolAddress((void**)&qkvl, g_qkvl);
    cudaGetSymbolAddress((void**)&ph,   g_ph);   cudaGetSymbolAddress((void**)&pl,   g_pl);
    cudaGetSymbolAddress((void**)&oh,   g_oh);   cudaGetSymbolAddress((void**)&ol,   g_ol);
    cudaGetSymbolAddress((void**)&ffh,  g_ffh);  cudaGetSymbolAddress((void**)&ffl,  g_ffl);
    bf16 *wqkvh,*wqkvl,*woh,*wol,*w1h,*w1l,*w2h,*w2l;
    cudaGetSymbolAddress((void**)&wqkvh, g_wqkvh); cudaGetSymbolAddress((void**)&wqkvl, g_wqkvl);
    cudaGetSymbolAddress((void**)&woh,   g_woh);   cudaGetSymbolAddress((void**)&wol,   g_wol);
    cudaGetSymbolAddress((void**)&w1h,   g_w1h);   cudaGetSymbolAddress((void**)&w1l,   g_w1l);
    cudaGetSymbolAddress((void**)&w2h,   g_w2h);   cudaGetSymbolAddress((void**)&w2l,   g_w2l);

    // dynamic-smem opt-in per instantiation
    auto setlim = [](const void* fn, int bytes) {
        cudaFuncSetAttribute(fn, cudaFuncAttributeMaxDynamicSharedMemorySize, bytes);
    };
    constexpr int SM_QKV = smem_bytes(128,128,false);
    constexpr int SM_QK  = smem_bytes(128,128,true);
    constexpr int SM_PV  = smem_bytes(128, 64,false);
    constexpr int SM_N512= smem_bytes( 64,128,false);
    setlim((const void*)gemm_bf<128,128,2,false,4,0>, SM_QKV);
    setlim((const void*)gemm_bf<128,128,2,true, 3,1>, SM_QK);
    setlim((const void*)gemm_bf<128, 64,2,false,4,2>, SM_PV);
    setlim((const void*)gemm_bf< 64,128,4,false,1,0>, SM_N512);
    setlim((const void*)gemm_bf<128,128,2,false,2,0>, SM_QKV);

    const int M = NB * NT;  // 4096

    copy_x_kernel<<<(NB*NT*ND)/256, 256>>>(tokens);
    build_bias_kernel<<<dim3(NT, NB), 256>>>(xy, alive, species);
    // weight conversion (once per launch)
    convert_qkv<<<(long)NL*ND*N3/256, 256>>>(Wq, Wk, Wv);
    convert_flat<<<(long)NL*ND*ND /256, 256>>>(Wo, woh, wol);
    convert_flat<<<(long)NL*ND*NFF/256, 256>>>(W1, w1h, w1l);
    convert_flat<<<(long)NL*NFF*ND/256, 256>>>(W2, w2h, w2l);

    for (int l = 0; l < NL; l++) {
        ln_kernel<true><<<M, 256>>>(px, g1 + (long)l*ND, be1 + (long)l*ND,
                                    nullptr, hh, hl);
        // fused QKV: [4096,512] @ [512,1536]
        gemm_bf<128,128,2,false,4,0><<<dim3(12,32), 256, SM_QKV>>>(
            hh, hl, wqkvh + (long)l*ND*N3, wqkvl + (long)l*ND*N3,
            nullptr, qkvh, qkvl, M, ND, ND, N3, N3, 1.0f, nullptr, nullptr, nullptr);
        // scores = QK^T/8 + bias
        gemm_bf<128,128,2,true,3,1><<<dim3(8,8,NB*NH), 256, SM_QK>>>(
            qkvh, qkvl, qkvh, qkvl, pscores, nullptr, nullptr,
            NT, NDH, N3, N3, NT, 0.125f, nullptr, nullptr, pbias);
        softmax_kernel<<<NB*NH*NT, 256>>>();
        // o = P @ V
        gemm_bf<128,64,2,false,4,2><<<dim3(1,8,NB*NH), 256, SM_PV>>>(
            ph, pl, qkvh, qkvl, nullptr, oh, ol,
            NT, NT, NT, N3, ND, 1.0f, nullptr, nullptr, nullptr);
        // x = x + o @ Wo + bo
        gemm_bf<64,128,4,false,1,0><<<dim3(4,64), 256, SM_N512>>>(
            oh, ol, woh + (long)l*ND*ND, wol + (long)l*ND*ND,
            px, nullptr, nullptr, M, ND, ND, ND, ND, 1.0f,
            bo + (long)l*ND, px, nullptr);
        ln_kernel<true><<<M, 256>>>(px, g2 + (long)l*ND, be2 + (long)l*ND,
                                    nullptr, hh, hl);
        // ff = gelu(h @ W1 + b1)
        gemm_bf<128,128,2,false,2,0><<<dim3(16,32), 256, SM_QKV>>>(
            hh, hl, w1h + (long)l*ND*NFF, w1l + (long)l*ND*NFF,
            nullptr, ffh, ffl, M, ND, ND, NFF, NFF, 1.0f,
            b1 + (long)l*NFF, nullptr, nullptr);
        // x = x + ff @ W2 + b2
        gemm_bf<64,128,4,false,1,0><<<dim3(4,64), 256, SM_N512>>>(
            ffh, ffl, w2h + (long)l*NFF*ND, w2l + (long)l*NFF*ND,
            px, nullptr, nullptr, M, NFF, NFF, ND, ND, 1.0f,
            b2 + (long)l*ND, px, nullptr);
    }

    ln_kernel<false><<<M, 256>>>(px, gf, bf, out, nullptr, nullptr);
}

// round 8
// speedup vs baseline: 2.9417x; 1.2254x over previous
#include <cuda_runtime.h>
#include <cuda_bf16.h>
#include <math.h>

typedef __nv_bfloat16 bf16;

// Problem constants
constexpr int NB  = 4;
constexpr int NT  = 1024;
constexpr int ND  = 512;
constexpr int NH  = 8;
constexpr int NL  = 6;
constexpr int NFF = 2048;
constexpr int NDH = 64;
constexpr int N3  = 3 * ND;   // 1536 (fused QKV width)
constexpr float NEG_INF = -1000000000.0f;
constexpr float R2      = 100.0f;
constexpr float EPS_LN  = 1e-5f;

// fp32 state
__device__ float g_x[NB*NT*ND];

// bf16 hi/lo activations
__device__ bf16 g_hh [NB*NT*ND],  g_hl [NB*NT*ND];
__device__ bf16 g_qkvh[NB*NT*N3], g_qkvl[NB*NT*N3];
__device__ bf16 g_oh [NB*NT*ND],  g_ol [NB*NT*ND];
__device__ bf16 g_ffh[NB*NT*NFF], g_ffl[NB*NT*NFF];

// bf16 hi/lo weights (converted once per launch)
__device__ bf16 g_wqkvh[NL*ND*N3], g_wqkvl[NL*ND*N3];
__device__ bf16 g_woh [NL*ND*ND],  g_wol [NL*ND*ND];
__device__ bf16 g_w1h [NL*ND*NFF], g_w1l [NL*ND*NFF];
__device__ bf16 g_w2h [NL*NFF*ND], g_w2l [NL*NFF*ND];

// ---------------------------------------------------------------------------
__device__ __forceinline__ void split1(float v, bf16& h, bf16& l) {
    h = __float2bfloat16(v);
    l = __float2bfloat16(v - __bfloat162float(h));
}
__device__ __forceinline__ void split_pack2(float a, float b, unsigned& h, unsigned& l) {
    bf16 ha = __float2bfloat16(a), hb = __float2bfloat16(b);
    bf16 la = __float2bfloat16(a - __bfloat162float(ha));
    bf16 lb = __float2bfloat16(b - __bfloat162float(hb));
    __nv_bfloat162 th = __halves2bfloat162(ha, hb);
    __nv_bfloat162 tl = __halves2bfloat162(la, lb);
    h = *(unsigned*)&th; l = *(unsigned*)&tl;
}

__global__ void copy_x_kernel(const float* __restrict__ src) {
    long i = (long)blockIdx.x * blockDim.x + threadIdx.x;
    g_x[i] = src[i];
}

__global__ void convert_flat(const float* __restrict__ s,
                             bf16* __restrict__ h, bf16* __restrict__ l) {
    long i = (long)blockIdx.x * 256 + threadIdx.x;
    split1(s[i], h[i], l[i]);
}

__global__ void convert_qkv(const float* __restrict__ Wq,
                            const float* __restrict__ Wk,
                            const float* __restrict__ Wv) {
    long i = (long)blockIdx.x * 256 + threadIdx.x;   // over NL*ND*N3
    int n = (int)(i % N3);
    long rem = i / N3;                                // l*ND + k
    const float* src = (n < ND) ? Wq : (n < 2*ND ? Wk : Wv);
    int nn = n & (ND - 1);
    split1(src[rem*ND + nn], g_wqkvh[i], g_wqkvl[i]);
}

// ---------------------------------------------------------------------------
// LayerNorm; BF=true -> bf16 hi/lo outputs, else fp32.
template<bool BF>
__global__ void ln_kernel(const float* __restrict__ x,
                          const float* __restrict__ g,
                          const float* __restrict__ be,
                          float* __restrict__ outf,
                          bf16* __restrict__ outh, bf16* __restrict__ outl) {
    __shared__ float sh[8];
    long row = blockIdx.x;
    const float* xr = x + row*ND;
    int t = threadIdx.x;
    float v0 = xr[t], v1 = xr[t + 256];

    float s = v0 + v1;
    #pragma unroll
    for (int o = 16; o > 0; o >>= 1) s += __shfl_xor_sync(0xffffffffu, s, o);
    if ((t & 31) == 0) sh[t >> 5] = s;
    __syncthreads();
    if (t < 8) {
        float w = sh[t];
        #pragma unroll
        for (int o = 4; o > 0; o >>= 1) w += __shfl_xor_sync(0xffu, w, o);
        if (t == 0) sh[0] = w;
    }
    __syncthreads();
    float mean = sh[0] * (1.0f / ND);
    __syncthreads();

    float d0 = v0 - mean, d1 = v1 - mean;
    float q = d0*d0 + d1*d1;
    #pragma unroll
    for (int o = 16; o > 0; o >>= 1) q += __shfl_xor_sync(0xffffffffu, q, o);
    if ((t & 31) == 0) sh[t >> 5] = q;
    __syncthreads();
    if (t < 8) {
        float w = sh[t];
        #pragma unroll
        for (int o = 4; o > 0; o >>= 1) w += __shfl_xor_sync(0xffu, w, o);
        if (t == 0) sh[0] = w;
    }
    __syncthreads();
    float rstd = rsqrtf(sh[0] * (1.0f / ND) + EPS_LN);

    float r0 = d0 * rstd * g[t]       + be[t];
    float r1 = d1 * rstd * g[t + 256] + be[t + 256];
    if (BF) {
        split1(r0, outh[row*ND + t],       outl[row*ND + t]);
        split1(r1, outh[row*ND + t + 256], outl[row*ND + t + 256]);
    } else {
        outf[row*ND + t]       = r0;
        outf[row*ND + t + 256] = r1;
    }
}

// ---------------------------------------------------------------------------
// mma / ldmatrix / cp.async primitives
__device__ __forceinline__ void ldsm4(unsigned* r, const bf16* p) {
    unsigned a = (unsigned)__cvta_generic_to_shared(p);
    asm volatile("ldmatrix.sync.aligned.m8n8.x4.shared.b16 {%0,%1,%2,%3}, [%4];"
                 : "=r"(r[0]), "=r"(r[1]), "=r"(r[2]), "=r"(r[3]) : "r"(a));
}
__device__ __forceinline__ void ldsm4t(unsigned* r, const bf16* p) {
    unsigned a = (unsigned)__cvta_generic_to_shared(p);
    asm volatile("ldmatrix.sync.aligned.m8n8.x4.trans.shared.b16 {%0,%1,%2,%3}, [%4];"
                 : "=r"(r[0]), "=r"(r[1]), "=r"(r[2]), "=r"(r[3]) : "r"(a));
}
__device__ __forceinline__ void mma_bf16(float* d, const unsigned* a, const unsigned* b) {
    asm volatile(
        "mma.sync.aligned.m16n8k16.row.col.f32.bf16.bf16.f32 "
        "{%0,%1,%2,%3},{%4,%5,%6,%7},{%8,%9},{%0,%1,%2,%3};"
        : "+f"(d[0]), "+f"(d[1]), "+f"(d[2]), "+f"(d[3])
        : "r"(a[0]), "r"(a[1]), "r"(a[2]), "r"(a[3]), "r"(b[0]), "r"(b[1]));
}
__device__ __forceinline__ void cpa16(bf16* dst, const bf16* src) {
    unsigned d = (unsigned)__cvta_generic_to_shared(dst);
    asm volatile("cp.async.cg.shared.global [%0], [%1], 16;" :: "r"(d), "l"(src));
}
__device__ __forceinline__ void cp_commit() { asm volatile("cp.async.commit_group;"); }
template<int N>
__device__ __forceinline__ void cp_wait() { asm volatile("cp.async.wait_group %0;" :: "n"(N)); }

// ---------------------------------------------------------------------------
// Fused flash attention per (q-tile 128, b*h). 8 warps, each owns 16 q-rows.
// Reads g_qkv hi/lo; computes S=QK^T/8 + inline bias; online softmax; O=P@V;
// writes g_oh/g_ol. 3-pass hi/lo arithmetic throughout (fp32-grade).
constexpr int APAD  = 72;                       // row pad (144B stride, conflict-free)
constexpr int ATILE = 128 * APAD;               // bf16 elems per tile plane (9216)
constexpr int AQH = 0, AQL = ATILE;
constexpr int AST = 2 * ATILE;                  // K/V stages start (bf16 units)
constexpr int ASTAGE = 4 * ATILE;               // KH,KL,VH,VL
constexpr int AMASK_BYTES = (AST + 2*ASTAGE) * 2;   // 184320
constexpr int ASMEM = AMASK_BYTES + 3 * 1024 * 4;   // + xk,yk,flag = 196608

__global__ void __launch_bounds__(256, 1)
attn_kernel(const float* __restrict__ xy,
            const int* __restrict__ alive,
            const int* __restrict__ species) {
    extern __shared__ bf16 sm[];
    float* skx = (float*)((char*)sm + AMASK_BYTES);
    float* sky = skx + 1024;
    int*   sfl = (int*)(sky + 1024);

    int z = blockIdx.y, b = z >> 3, h = z & 7;
    int row0 = blockIdx.x * 128;
    int tid = threadIdx.x, wid = tid >> 5, lane = tid & 31;
    int gid = lane >> 2, tig = lane & 3;
    int wrow = wid * 16;

    const bf16* qh = g_qkvh + (long)b*NT*N3 + h*NDH;
    const bf16* ql = g_qkvl + (long)b*NT*N3 + h*NDH;
    const bf16* kh = qh + ND, *kl = ql + ND;
    const bf16* vh = qh + 2*ND, *vl = ql + 2*ND;

    // ---- stage Q (group 1) + mask tables (regular stores) ----
    #pragma unroll
    for (int f = tid; f < 128*8; f += 256) {
        int row = f >> 3, ck = (f & 7) * 8;
        cpa16(sm + AQH + row*APAD + ck, qh + (long)(row0 + row)*N3 + ck);
        cpa16(sm + AQL + row*APAD + ck, ql + (long)(row0 + row)*N3 + ck);
    }
    #pragma unroll
    for (int j = tid; j < 1024; j += 256) {
        skx[j] = xy[((long)b*NT + j)*2 + 0];
        sky[j] = xy[((long)b*NT + j)*2 + 1];
        sfl[j] = (alive[(long)b*NT + j] == 0 ? 1 : 0)
               | (species[(long)b*NT + j] < 2 ? 2 : 0);
    }
    cp_commit();

    auto stageKV = [&](int jt, int p) {
        bf16* base = sm + AST + p*ASTAGE;
        int jb = jt * 128;
        #pragma unroll
        for (int f = tid; f < 128*8; f += 256) {
            int row = f >> 3, ck = (f & 7) * 8;
            long go = (long)(jb + row)*N3 + ck;
            cpa16(base + 0*ATILE + row*APAD + ck, kh + go);
            cpa16(base + 1*ATILE + row*APAD + ck, kl + go);
            cpa16(base + 2*ATILE + row*APAD + ck, vh + go);
            cpa16(base + 3*ATILE + row*APAD + ck, vl + go);
        }
    };
    stageKV(0, 0);
    cp_commit();
    cp_wait<1>();          // Q group done
    __syncthreads();

    // ---- Q fragments (rows wrow..wrow+16, 4 k16 chunks, hi/lo) ----
    int r_ld = (lane & 7) + ((lane >> 3) & 1) * 8;
    int c_ld = (lane >> 4) * 8;
    unsigned qfh[4][4], qfl[4][4];
    #pragma unroll
    for (int ks = 0; ks < 4; ks++) {
        ldsm4(qfh[ks], sm + AQH + (wrow + r_ld)*APAD + ks*16 + c_ld);
        ldsm4(qfl[ks], sm + AQL + (wrow + r_ld)*APAD + ks*16 + c_ld);
    }

    // ---- per-thread q-side data ----
    int r0 = row0 + wrow + gid, r1 = r0 + 8;
    float xq0 = xy[((long)b*NT + r0)*2], yq0 = xy[((long)b*NT + r0)*2 + 1];
    float xq1 = xy[((long)b*NT + r1)*2], yq1 = xy[((long)b*NT + r1)*2 + 1];
    int aq0 = species[(long)b*NT + r0] < 2 ? 1 : 0;
    int aq1 = species[(long)b*NT + r1] < 2 ? 1 : 0;

    float m0 = -INFINITY, m1 = -INFINITY, l0 = 0.0f, l1 = 0.0f;
    float oacc[8][4];
    #pragma unroll
    for (int i = 0; i < 8; i++)
        #pragma unroll
        for (int e = 0; e < 4; e++) oacc[i][e] = 0.0f;

    for (int jt = 0; jt < 8; jt++) {
        int p = jt & 1;
        if (jt < 7) stageKV(jt + 1, p ^ 1);
        cp_commit();
        cp_wait<1>();
        __syncthreads();

        bf16* sKh = sm + AST + p*ASTAGE;
        bf16* sKl = sKh + ATILE;
        bf16* sVh = sKh + 2*ATILE;
        bf16* sVl = sKh + 3*ATILE;

        // ---- S = Q @ K^T (3-pass) ----
        float sacc[16][4];
        #pragma unroll
        for (int i = 0; i < 16; i++)
            #pragma unroll
            for (int e = 0; e < 4; e++) sacc[i][e] = 0.0f;

        #pragma unroll
        for (int ks = 0; ks < 4; ks++) {
            #pragma unroll
            for (int np = 0; np < 8; np++) {
                int nrow = np*16 + (lane >> 4)*8 + (lane & 7);
                int kcol = ks*16 + ((lane >> 3) & 1)*8;
                unsigned rh[4], rl[4];
                ldsm4(rh, sKh + nrow*APAD + kcol);
                ldsm4(rl, sKl + nrow*APAD + kcol);
                unsigned bh0[2] = {rh[0], rh[1]}, bh1[2] = {rh[2], rh[3]};
                unsigned bl0[2] = {rl[0], rl[1]}, bl1[2] = {rl[2], rl[3]};
                mma_bf16(sacc[2*np],   qfh[ks], bh0);
                mma_bf16(sacc[2*np],   qfh[ks], bl0);
                mma_bf16(sacc[2*np],   qfl[ks], bh0);
                mma_bf16(sacc[2*np+1], qfh[ks], bh1);
                mma_bf16(sacc[2*np+1], qfh[ks], bl1);
                mma_bf16(sacc[2*np+1], qfl[ks], bh1);
            }
        }

        // ---- scale + inline bias + tile max ----
        int jbase = jt * 128;
        float tm0 = -INFINITY, tm1 = -INFINITY;
        #pragma unroll
        for (int nt = 0; nt < 16; nt++) {
            int j0 = jbase + nt*8 + 2*tig, j1 = j0 + 1;
            float kx0 = skx[j0], ky0 = sky[j0]; int f0 = sfl[j0];
            float kx1 = skx[j1], ky1 = sky[j1]; int f1 = sfl[j1];
            float dx, dy, bb;
            dx = xq0-kx0; dy = yq0-ky0; bb = 0.0f;
            if (f0 & 1) bb += NEG_INF;
            if (dx*dx + dy*dy > R2) bb += NEG_INF;
            if (aq0 ^ ((f0 >> 1) & 1)) bb += NEG_INF;
            sacc[nt][0] = sacc[nt][0]*0.125f + bb;
            dx = xq0-kx1; dy = yq0-ky1; bb = 0.0f;
            if (f1 & 1) bb += NEG_INF;
            if (dx*dx + dy*dy > R2) bb += NEG_INF;
            if (aq0 ^ ((f1 >> 1) & 1)) bb += NEG_INF;
            sacc[nt][1] = sacc[nt][1]*0.125f + bb;
            dx = xq1-kx0; dy = yq1-ky0; bb = 0.0f;
            if (f0 & 1) bb += NEG_INF;
            if (dx*dx + dy*dy > R2) bb += NEG_INF;
            if (aq1 ^ ((f0 >> 1) & 1)) bb += NEG_INF;
            sacc[nt][2] = sacc[nt][2]*0.125f + bb;
            dx = xq1-kx1; dy = yq1-ky1; bb = 0.0f;
            if (f1 & 1) bb += NEG_INF;
            if (dx*dx + dy*dy > R2) bb += NEG_INF;
            if (aq1 ^ ((f1 >> 1) & 1)) bb += NEG_INF;
            sacc[nt][3] = sacc[nt][3]*0.125f + bb;
            tm0 = fmaxf(tm0, fmaxf(sacc[nt][0], sacc[nt][1]));
            tm1 = fmaxf(tm1, fmaxf(sacc[nt][2], sacc[nt][3]));
        }
        tm0 = fmaxf(tm0, __shfl_xor_sync(0xffffffffu, tm0, 1));
        tm0 = fmaxf(tm0, __shfl_xor_sync(0xffffffffu, tm0, 2));
        tm1 = fmaxf(tm1, __shfl_xor_sync(0xffffffffu, tm1, 1));
        tm1 = fmaxf(tm1, __shfl_xor_sync(0xffffffffu, tm1, 2));

        float m0n = fmaxf(m0, tm0), m1n = fmaxf(m1, tm1);
        float c0 = __expf(m0 - m0n), c1 = __expf(m1 - m1n);
        l0 *= c0; l1 *= c1;
        #pragma unroll
        for (int i = 0; i < 8; i++) {
            oacc[i][0] *= c0; oacc[i][1] *= c0;
            oacc[i][2] *= c1; oacc[i][3] *= c1;
        }

        // ---- P = exp(S - m), P @ V (3-pass) ----
        float rs0 = 0.0f, rs1 = 0.0f;
        #pragma unroll
        for (int kc = 0; kc < 8; kc++) {
            float p00 = __expf(sacc[2*kc][0]   - m0n);
            float p01 = __expf(sacc[2*kc][1]   - m0n);
            float p10 = __expf(sacc[2*kc][2]   - m1n);
            float p11 = __expf(sacc[2*kc][3]   - m1n);
            float p20 = __expf(sacc[2*kc+1][0] - m0n);
            float p21 = __expf(sacc[2*kc+1][1] - m0n);
            float p30 = __expf(sacc[2*kc+1][2] - m1n);
            float p31 = __expf(sacc[2*kc+1][3] - m1n);
            rs0 += p00 + p01 + p20 + p21;
            rs1 += p10 + p11 + p30 + p31;
            unsigned ah[4], al[4];
            split_pack2(p00, p01, ah[0], al[0]);
            split_pack2(p10, p11, ah[1], al[1]);
            split_pack2(p20, p21, ah[2], al[2]);
            split_pack2(p30, p31, ah[3], al[3]);
            int krow = kc*16 + ((lane >> 3) & 1)*8 + (lane & 7);
            #pragma unroll
            for (int np = 0; np < 4; np++) {           // 4 x 16 = all 64 V cols
                int ncol = np*16 + (lane >> 4)*8;
                unsigned rh[4], rl[4];
                ldsm4t(rh, sVh + krow*APAD + ncol);
                ldsm4t(rl, sVl + krow*APAD + ncol);
                unsigned bh0[2] = {rh[0], rh[1]}, bh1[2] = {rh[2], rh[3]};
                unsigned bl0[2] = {rl[0], rl[1]}, bl1[2] = {rl[2], rl[3]};
                mma_bf16(oacc[2*np],   ah, bh0);
                mma_bf16(oacc[2*np],   ah, bl0);
                mma_bf16(oacc[2*np],   al, bh0);
                mma_bf16(oacc[2*np+1], ah, bh1);
                mma_bf16(oacc[2*np+1], ah, bl1);
                mma_bf16(oacc[2*np+1], al, bh1);
            }
        }
        rs0 += __shfl_xor_sync(0xffffffffu, rs0, 1);
        rs0 += __shfl_xor_sync(0xffffffffu, rs0, 2);
        rs1 += __shfl_xor_sync(0xffffffffu, rs1, 1);
        rs1 += __shfl_xor_sync(0xffffffffu, rs1, 2);
        l0 += rs0; l1 += rs1;
        m0 = m0n; m1 = m1n;
        __syncthreads();
    }

    // ---- normalize + store O (bf16 hi/lo) ----
    float inv0 = 1.0f / l0, inv1 = 1.0f / l1;
    #pragma unroll
    for (int nt = 0; nt < 8; nt++) {
        int cabs = h*NDH + nt*8 + 2*tig;
        long off0 = ((long)b*NT + r0)*ND + cabs;
        long off1 = ((long)b*NT + r1)*ND + cabs;
        unsigned hh_, ll_;
        split_pack2(oacc[nt][0]*inv0, oacc[nt][1]*inv0, hh_, ll_);
        *(unsigned*)(g_oh + off0) = hh_; *(unsigned*)(g_ol + off0) = ll_;
        split_pack2(oacc[nt][2]*inv1, oacc[nt][3]*inv1, hh_, ll_);
        *(unsigned*)(g_oh + off1) = hh_; *(unsigned*)(g_ol + off1) = ll_;
    }
}

// ---------------------------------------------------------------------------
// bf16 hi/lo 3-pass GEMM, cp.async double-buffered, dynamic smem.
// EPI: 1 +bvec+res -> f32 | 2 gelu -> bf16 hi/lo | 4 plain -> bf16 hi/lo
template<int BM, int BN, int WN, int EPI>
__global__ void __launch_bounds__(256, 2)
gemm_bf(const bf16* __restrict__ Agh, const bf16* __restrict__ Agl,
        const bf16* __restrict__ Bgh, const bf16* __restrict__ Bgl,
        float* __restrict__ Cf, bf16* __restrict__ Ch, bf16* __restrict__ Cl,
        int M, int K, int lda, int ldb, int ldc,
        const float* __restrict__ bvec, const float* __restrict__ res) {
    constexpr int WM    = 8 / WN;
    constexpr int MT    = BM / WM / 16;
    constexpr int NTW   = BN / WN / 8;
    constexpr int PADK  = 40;
    constexpr int BCOLS = BN + 8;
    constexpr int AE    = BM * PADK;
    constexpr int BE    = 32 * BCOLS;
    constexpr int STAGE = 2*AE + 2*BE;

    extern __shared__ bf16 sm[];

    int tid = threadIdx.x, wid = tid >> 5, lane = tid & 31;
    int wm = wid % WM, wn = wid / WM;
    int wrow = wm * (BM / WM), wcol = wn * (BN / WN);
    int row0 = blockIdx.y * BM, col0 = blockIdx.x * BN;

    float acc[MT][NTW][4];
    #pragma unroll
    for (int i = 0; i < MT; i++)
        #pragma unroll
        for (int j = 0; j < NTW; j++)
            #pragma unroll
            for (int e = 0; e < 4; e++) acc[i][j][e] = 0.0f;

    int r_ld = (lane & 7) + ((lane >> 3) & 1) * 8;
    int c_ld = (lane >> 4) * 8;

    const int NS = K / 32;

    auto stage = [&](int s, int p) {
        bf16* sAh = sm + p*STAGE;
        bf16* sAl = sAh + AE;
        bf16* sBh = sAh + 2*AE;
        bf16* sBl = sBh + BE;
        int k0 = s * 32;
        #pragma unroll
        for (int f = tid; f < BM*4; f += 256) {
            int row = f >> 2, ck = (f & 3) * 8;
            long go = (long)(row0 + row)*lda + k0 + ck;
            cpa16(sAh + row*PADK + ck, Agh + go);
            cpa16(sAl + row*PADK + ck, Agl + go);
        }
        #pragma unroll
        for (int f = tid; f < 32*(BN/8); f += 256) {
            int row = f / (BN/8), ck = (f % (BN/8)) * 8;
            long go = (long)(k0 + row)*ldb + col0 + ck;
            cpa16(sBh + row*BCOLS + ck, Bgh + go);
            cpa16(sBl + row*BCOLS + ck, Bgl + go);
        }
    };

    stage(0, 0);
    cp_commit();

    for (int s = 0; s < NS; s++) {
        int p = s & 1;
        if (s + 1 < NS) stage(s + 1, p ^ 1);
        cp_commit();
        cp_wait<1>();
        __syncthreads();

        bf16* sAh = sm + p*STAGE;
        bf16* sAl = sAh + AE;
        bf16* sBh = sAh + 2*AE;
        bf16* sBl = sBh + BE;

        #pragma unroll
        for (int ks = 0; ks < 2; ks++) {
            unsigned afr[MT][2][4];
            unsigned bfr[NTW][2][2];
            #pragma unroll
            for (int mt = 0; mt < MT; mt++) {
                ldsm4(afr[mt][0], sAh + (wrow + mt*16 + r_ld)*PADK + ks*16 + c_ld);
                ldsm4(afr[mt][1], sAl + (wrow + mt*16 + r_ld)*PADK + ks*16 + c_ld);
            }
            #pragma unroll
            for (int np = 0; np < NTW/2; np++) {
                unsigned r[4];
                int krow = ks*16 + ((lane >> 3) & 1)*8 + (lane & 7);
                int ncol = wcol + np*16 + (lane >> 4)*8;
                ldsm4t(r, sBh + krow*BCOLS + ncol);
                bfr[2*np][0][0] = r[0]; bfr[2*np][0][1] = r[1];
                bfr[2*np+1][0][0] = r[2]; bfr[2*np+1][0][1] = r[3];
                ldsm4t(r, sBl + krow*BCOLS + ncol);
                bfr[2*np][1][0] = r[0]; bfr[2*np][1][1] = r[1];
                bfr[2*np+1][1][0] = r[2]; bfr[2*np+1][1][1] = r[3];
            }
            #pragma unroll
            for (int mt = 0; mt < MT; mt++)
                #pragma unroll
                for (int nt = 0; nt < NTW; nt++) {
                    mma_bf16(acc[mt][nt], afr[mt][0], bfr[nt][0]);
                    mma_bf16(acc[mt][nt], afr[mt][0], bfr[nt][1]);
                    mma_bf16(acc[mt][nt], afr[mt][1], bfr[nt][0]);
                }
        }
        __syncthreads();
    }

    int gid = lane >> 2, tig = lane & 3;
    #pragma unroll
    for (int mt = 0; mt < MT; mt++) {
        #pragma unroll
        for (int nt = 0; nt < NTW; nt++) {
            int r = row0 + wrow + mt*16 + gid;
            int c = col0 + wcol + nt*8 + 2*tig;
            #pragma unroll
            for (int half = 0; half < 2; half++) {
                int rr = r + half*8;
                float d0 = acc[mt][nt][2*half + 0];
                float d1 = acc[mt][nt][2*half + 1];
                long off = (long)rr*ldc + c;
                if (EPI == 1) {
                    d0 += bvec[c]   + res[off];
                    d1 += bvec[c+1] + res[off + 1];
                    *(float2*)(Cf + off) = make_float2(d0, d1);
                } else if (EPI == 2) {
                    float u0 = d0 + bvec[c],   u1 = d1 + bvec[c+1];
                    d0 = 0.5f * u0 * (1.0f + erff(u0 * 0.70710678118654752f));
                    d1 = 0.5f * u1 * (1.0f + erff(u1 * 0.70710678118654752f));
                    unsigned hh_, ll_;
                    split_pack2(d0, d1, hh_, ll_);
                    *(unsigned*)(Ch + off) = hh_;
                    *(unsigned*)(Cl + off) = ll_;
                } else {  // EPI == 4
                    unsigned hh_, ll_;
                    split_pack2(d0, d1, hh_, ll_);
                    *(unsigned*)(Ch + off) = hh_;
                    *(unsigned*)(Cl + off) = ll_;
                }
            }
        }
    }
}

constexpr int smem_gemm(int BM, int BN) {
    return 8 * (BM*40 + 32*(BN+8));
}

// ---------------------------------------------------------------------------
extern "C" void kernel_launch(void* const* d_in, const int* in_sizes, int n_in,
                              void* d_out, int out_size) {
    const float* tokens  = (const float*)d_in[0];
    const float* xy      = (const float*)d_in[1];
    const float* Wq      = (const float*)d_in[2];
    const float* Wk      = (const float*)d_in[3];
    const float* Wv      = (const float*)d_in[4];
    const float* Wo      = (const float*)d_in[5];
    const float* bo      = (const float*)d_in[6];
    const float* W1      = (const float*)d_in[7];
    const float* b1      = (const float*)d_in[8];
    const float* W2      = (const float*)d_in[9];
    const float* b2      = (const float*)d_in[10];
    const float* g1      = (const float*)d_in[11];
    const float* be1     = (const float*)d_in[12];
    const float* g2      = (const float*)d_in[13];
    const float* be2     = (const float*)d_in[14];
    const float* gf      = (const float*)d_in[15];
    const float* bf      = (const float*)d_in[16];
    const int*   alive   = (const int*)d_in[17];
    const int*   species = (const int*)d_in[18];
    float* out = (float*)d_out;

    float *px;
    cudaGetSymbolAddress((void**)&px, g_x);
    bf16 *hh,*hl,*qkvh,*qkvl,*oh,*ol,*ffh,*ffl;
    cudaGetSymbolAddress((void**)&hh,   g_hh);   cudaGetSymbolAddress((void**)&hl,   g_hl);
    cudaGetSymbolAddress((void**)&qkvh, g_qkvh); cudaGetSymbolAddress((void**)&qkvl, g_qkvl);
    cudaGetSymbolAddress((void**)&oh,   g_oh);   cudaGetSymbolAddress((void**)&ol,   g_ol);
    cudaGetSymbolAddress((void**)&ffh,  g_ffh);  cudaGetSymbolAddress((void**)&ffl,  g_ffl);
    bf16 *wqkvh,*wqkvl,*woh,*wol,*w1h,*w1l,*w2h,*w2l;
    cudaGetSymbolAddress((void**)&wqkvh, g_wqkvh); cudaGetSymbolAddress((void**)&wqkvl, g_wqkvl);
    cudaGetSymbolAddress((void**)&woh,   g_woh);   cudaGetSymbolAddress((void**)&wol,   g_wol);
    cudaGetSymbolAddress((void**)&w1h,   g_w1h);   cudaGetSymbolAddress((void**)&w1l,   g_w1l);
    cudaGetSymbolAddress((void**)&w2h,   g_w2h);   cudaGetSymbolAddress((void**)&w2l,   g_w2l);

    auto setlim = [](const void* fn, int bytes) {
        cudaFuncSetAttribute(fn, cudaFuncAttributeMaxDynamicSharedMemorySize, bytes);
    };
    constexpr int SM_BIG  = smem_gemm(128,128);
    constexpr int SM_N512 = smem_gemm( 64,128);
    setlim((const void*)gemm_bf<128,128,2,4>, SM_BIG);
    setlim((const void*)gemm_bf<128,128,2,2>, SM_BIG);
    setlim((const void*)gemm_bf< 64,128,4,1>, SM_N512);
    setlim((const void*)attn_kernel, ASMEM);

    const int M = NB * NT;  // 4096

    copy_x_kernel<<<(NB*NT*ND)/256, 256>>>(tokens);
    convert_qkv<<<(long)NL*ND*N3/256, 256>>>(Wq, Wk, Wv);
    convert_flat<<<(long)NL*ND*ND /256, 256>>>(Wo, woh, wol);
    convert_flat<<<(long)NL*ND*NFF/256, 256>>>(W1, w1h, w1l);
    convert_flat<<<(long)NL*NFF*ND/256, 256>>>(W2, w2h, w2l);

    for (int l = 0; l < NL; l++) {
        ln_kernel<true><<<M, 256>>>(px, g1 + (long)l*ND, be1 + (long)l*ND,
                                    nullptr, hh, hl);
        // fused QKV: [4096,512] @ [512,1536]
        gemm_bf<128,128,2,4><<<dim3(12,32), 256, SM_BIG>>>(
            hh, hl, wqkvh + (long)l*ND*N3, wqkvl + (long)l*ND*N3,
            nullptr, qkvh, qkvl, M, ND, ND, N3, N3, nullptr, nullptr);
        // fused flash attention -> o (bf16 hi/lo)
        attn_kernel<<<dim3(NT/128, NB*NH), 256, ASMEM>>>(xy, alive, species);
        // x = x + o @ Wo + bo
        gemm_bf<64,128,4,1><<<dim3(4,64), 256, SM_N512>>>(
            oh, ol, woh + (long)l*ND*ND, wol + (long)l*ND*ND,
            px, nullptr, nullptr, M, ND, ND, ND, ND,
            bo + (long)l*ND, px);
        ln_kernel<true><<<M, 256>>>(px, g2 + (long)l*ND, be2 + (long)l*ND,
                                    nullptr, hh, hl);
        // ff = gelu(h @ W1 + b1)
        gemm_bf<128,128,2,2><<<dim3(16,32), 256, SM_BIG>>>(
            hh, hl, w1h + (long)l*ND*NFF, w1l + (long)l*ND*NFF,
            nullptr, ffh, ffl, M, ND, ND, NFF, NFF,
            b1 + (long)l*NFF, nullptr);
        // x = x + ff @ W2 + b2
        gemm_bf<64,128,4,1><<<dim3(4,64), 256, SM_N512>>>(
            ffh, ffl, w2h + (long)l*NFF*ND, w2l + (long)l*NFF*ND,
            px, nullptr, nullptr, M, NFF, NFF, ND, ND,
            b2 + (long)l*ND, px);
    }

    ln_kernel<false><<<M, 256>>>(px, gf, bf, out, nullptr, nullptr);
}